// round 6
// baseline (speedup 1.0000x reference)
#include <cuda_runtime.h>
#include <cuda_bf16.h>

#define B_TOTAL 65536
#define DD      256
#define HH      16
#define TPB     224

__device__ __forceinline__ float tanhA(float v) {
    float y;
    asm("tanh.approx.f32 %0, %1;" : "=f"(y) : "f"(v));
    return y;
}

__global__ void __launch_bounds__(TPB, 2) kan_kernel(
    const float* __restrict__ x,
    const float* __restrict__ w1,
    const float* __restrict__ b1,
    const float* __restrict__ w2,
    const float* __restrict__ b2,
    float* __restrict__ out)
{
    // 3 * 256 * 16 floats = 48 KB static shared (exactly at the static limit)
    __shared__ float4 sw1[DD * HH / 4];
    __shared__ float4 sb1[DD * HH / 4];
    __shared__ float4 sw2[DD * HH / 4];

    const float4* gw1 = reinterpret_cast<const float4*>(w1);
    const float4* gb1 = reinterpret_cast<const float4*>(b1);
    const float4* gw2 = reinterpret_cast<const float4*>(w2);
    for (int i = threadIdx.x; i < DD * HH / 4; i += TPB) {
        sw1[i] = gw1[i];
        sb1[i] = gb1[i];
        sw2[i] = gw2[i];
    }
    __syncthreads();

    const int b = blockIdx.x * TPB + threadIdx.x;
    if (b >= B_TOTAL) return;

    // sum(b2): uniform-address loads, L1-resident after first touch, negligible.
    float accb = 0.0f;
    const float4* gb2 = reinterpret_cast<const float4*>(b2);
    #pragma unroll
    for (int i = 0; i < DD / 4; ++i) {
        float4 v = __ldg(&gb2[i]);
        accb += (v.x + v.y) + (v.z + v.w);
    }

    const float4* xr = reinterpret_cast<const float4*>(x + (size_t)b * DD);

    float acc0 = 0.0f, acc1 = 0.0f;

    float4 nxt = xr[0];   // software prefetch pipeline, distance 1
    #pragma unroll 1
    for (int d4 = 0; d4 < DD / 4; ++d4) {
        float4 xv = nxt;
        if (d4 + 1 < DD / 4) nxt = xr[d4 + 1];

        float xs[4] = {xv.x, xv.y, xv.z, xv.w};
        #pragma unroll
        for (int j = 0; j < 4; ++j) {
            const int base = (d4 * 4 + j) * (HH / 4);
            #pragma unroll
            for (int q = 0; q < 4; ++q) {
                float4 W1 = sw1[base + q];
                float4 B1 = sb1[base + q];
                float4 W2 = sw2[base + q];
                float t0 = tanhA(fmaf(xs[j], W1.x, B1.x));
                float t1 = tanhA(fmaf(xs[j], W1.y, B1.y));
                float t2 = tanhA(fmaf(xs[j], W1.z, B1.z));
                float t3 = tanhA(fmaf(xs[j], W1.w, B1.w));
                acc0 = fmaf(t0, W2.x, acc0);
                acc1 = fmaf(t1, W2.y, acc1);
                acc0 = fmaf(t2, W2.z, acc0);
                acc1 = fmaf(t3, W2.w, acc1);
            }
        }
    }

    out[b] = (acc0 + acc1) + accb;
}

extern "C" void kernel_launch(void* const* d_in, const int* in_sizes, int n_in,
                              void* d_out, int out_size) {
    const float* x  = (const float*)d_in[0];
    const float* w1 = (const float*)d_in[1];
    const float* b1 = (const float*)d_in[2];
    const float* w2 = (const float*)d_in[3];
    const float* b2 = (const float*)d_in[4];
    float* out = (float*)d_out;

    const int nblk = (B_TOTAL + TPB - 1) / TPB;   // 293 blocks -> max 2 blocks/SM
    kan_kernel<<<nblk, TPB>>>(x, w1, b1, w2, b2, out);
}